// round 5
// baseline (speedup 1.0000x reference)
#include <cuda_runtime.h>

#define BATCH 16
#define DIM   512
#define S     128
#define IMG   (S*S)          // 16384 floats per (b,c) plane
#define IMG4  (IMG/4)
#define CS    4              // channel splits in k1
#define CPS   (DIM/CS)       // 128 channels per split

#define SROW  129            // padded smem row (bank-conflict-free columns)
#define PLANE (S*SROW)       // padded plane floats

// partial channel-reduced planes: [split][b][o(2)][h][w]  (8 MB, L2-resident)
__device__ float g_x2p[CS * BATCH * 2 * IMG];

// ---------------------------------------------------------------------------
// k1: 1x1 conv channel reduction, 4-way channel split.
// 262144 threads, each owns one float4 along W for 128 channels.
// ---------------------------------------------------------------------------
__global__ __launch_bounds__(128) void swa_k1(const float* __restrict__ x,
                                              const float* __restrict__ w_conv) {
    __shared__ float w0[DIM];
    __shared__ float w1[DIM];
    for (int i = threadIdx.x; i < DIM; i += 128) {
        w0[i] = w_conv[i];
        w1[i] = w_conv[DIM + i];
    }
    __syncthreads();

    int tid   = blockIdx.x * 128 + threadIdx.x;   // 0..262143
    int split = tid >> 16;
    int rem   = tid & 65535;
    int b     = rem >> 12;
    int p     = rem & (IMG4 - 1);

    const float4* base = reinterpret_cast<const float4*>(x)
                       + (size_t)b * DIM * IMG4 + (size_t)split * CPS * IMG4 + p;
    const int cbase = split * CPS;

    float4 a0 = make_float4(0.f, 0.f, 0.f, 0.f);
    float4 a1 = make_float4(0.f, 0.f, 0.f, 0.f);

#pragma unroll 8
    for (int c = 0; c < CPS; c++) {
        float4 v = __ldcs(base + (size_t)c * IMG4);    // streaming, zero reuse
        float f0 = w0[cbase + c];
        float f1 = w1[cbase + c];
        a0.x = fmaf(f0, v.x, a0.x);  a0.y = fmaf(f0, v.y, a0.y);
        a0.z = fmaf(f0, v.z, a0.z);  a0.w = fmaf(f0, v.w, a0.w);
        a1.x = fmaf(f1, v.x, a1.x);  a1.y = fmaf(f1, v.y, a1.y);
        a1.z = fmaf(f1, v.z, a1.z);  a1.w = fmaf(f1, v.w, a1.w);
    }

    float4* out = reinterpret_cast<float4*>(g_x2p)
                + (size_t)split * (BATCH * 2 * IMG4)
                + (size_t)b * 2 * IMG4 + p;
    out[0]    = a0;
    out[IMG4] = a1;
}

// ---------------------------------------------------------------------------
// k2 (fused): stage plane -> strip convs (restructured, coalesced) ->
//             GEMV + sigmoid -> outer product.  One block per batch.
//
//   coldot[c,kw,w] = sum_h x2[c,h,w] * w_ww[c,h,kw]
//   ww_raw[wo]     = sum_{c,kw, 0<=wo-2+kw<128} coldot[c,kw,wo-2+kw]
//   rowdot[c,kh,h] = sum_w x2[c,h,w] * w_hw[c,kh,w]
//   hw_raw[ho]     = sum_{c,kh, 0<=ho-2+kh<128} rowdot[c,kh,ho-2+kh]
// ---------------------------------------------------------------------------
__global__ __launch_bounds__(256) void swa_k2(const float* __restrict__ w_ww,   // [2,128,5]
                                              const float* __restrict__ w_hw,   // [2,5,128]
                                              const float* __restrict__ ww_lw,  // [128,128]
                                              const float* __restrict__ ww_lb,
                                              const float* __restrict__ hw_lw,
                                              const float* __restrict__ hw_lb,
                                              float* __restrict__ out) {
    extern __shared__ float sm[];
    float* x2s    = sm;                       // 2 * 128 * 129 = 33024
    float* coldot = x2s + 2 * PLANE;          // 2*5*128 = 1280
    float* rowdot = coldot + 1280;            // 1280
    float* wwraw  = rowdot + 1280;            // 128
    float* hwraw  = wwraw + S;                // 128
    float* wwsig  = hwraw + S;                // 128
    float* hwsig  = wwsig + S;                // 128

    const int b = blockIdx.x;
    const int t = threadIdx.x;

    // --- stage: sum 4 split partials into padded smem plane (coalesced) ---
    {
        const float4* pb = reinterpret_cast<const float4*>(g_x2p) + (size_t)b * 2 * IMG4;
        const size_t  st = (size_t)BATCH * 2 * IMG4;
        for (int i = t; i < 2 * IMG4; i += 256) {
            float4 v0 = pb[i];
            float4 v1 = pb[i + st];
            float4 v2 = pb[i + 2 * st];
            float4 v3 = pb[i + 3 * st];
            int e = i << 2;                 // element index within [2][128][128]
            int c = e >> 14;
            int h = (e & 16383) >> 7;
            int w = e & 127;
            float* d = x2s + c * PLANE + h * SROW + w;
            d[0] = v0.x + v1.x + v2.x + v3.x;
            d[1] = v0.y + v1.y + v2.y + v3.y;
            d[2] = v0.z + v1.z + v2.z + v3.z;
            d[3] = v0.w + v1.w + v2.w + v3.w;
        }
    }
    __syncthreads();

    // --- coldot: thread = (c, w); column reduction over h, conflict-free ---
    {
        int c = t >> 7, w = t & 127;
        const float* col = x2s + c * PLANE + w;
        const float* wgt = w_ww + c * (S * 5);
        float a0 = 0.f, a1 = 0.f, a2 = 0.f, a3 = 0.f, a4 = 0.f;
#pragma unroll 4
        for (int h = 0; h < S; h++) {
            float v = col[h * SROW];
            const float* wr = wgt + h * 5;
            a0 = fmaf(v, wr[0], a0);
            a1 = fmaf(v, wr[1], a1);
            a2 = fmaf(v, wr[2], a2);
            a3 = fmaf(v, wr[3], a3);
            a4 = fmaf(v, wr[4], a4);
        }
        float* cd = coldot + c * (5 * S) + w;
        cd[0*S] = a0; cd[1*S] = a1; cd[2*S] = a2; cd[3*S] = a3; cd[4*S] = a4;
    }

    // --- rowdot: thread = (c, h); row reduction over w, pad makes it clean ---
    {
        int c = t >> 7, h = t & 127;
        const float* row = x2s + c * PLANE + h * SROW;
        const float* wgt = w_hw + c * (5 * S);
        float a0 = 0.f, a1 = 0.f, a2 = 0.f, a3 = 0.f, a4 = 0.f;
#pragma unroll 4
        for (int w = 0; w < S; w++) {
            float v = row[w];
            a0 = fmaf(v, wgt[0*S + w], a0);
            a1 = fmaf(v, wgt[1*S + w], a1);
            a2 = fmaf(v, wgt[2*S + w], a2);
            a3 = fmaf(v, wgt[3*S + w], a3);
            a4 = fmaf(v, wgt[4*S + w], a4);
        }
        float* rd = rowdot + c * (5 * S) + h;
        rd[0*S] = a0; rd[1*S] = a1; rd[2*S] = a2; rd[3*S] = a3; rd[4*S] = a4;
    }
    __syncthreads();

    // --- combine taps (boundary-guarded) ---
    if (t < S) {
        float sw = 0.f, sh = 0.f;
#pragma unroll
        for (int k = 0; k < 5; k++) {
            int i = t - 2 + k;
            if (i >= 0 && i < S) {
                sw += coldot[k * S + i] + coldot[(5 + k) * S + i];
                sh += rowdot[k * S + i] + rowdot[(5 + k) * S + i];
            }
        }
        wwraw[t] = sw;
        hwraw[t] = sh;
    }
    __syncthreads();

    // --- linear + sigmoid ---
    if (t < S) {
        float sw = ww_lb[t];
        float sh = hw_lb[t];
        const float* wwr = ww_lw + t * S;
        const float* hwr = hw_lw + t * S;
#pragma unroll 4
        for (int k = 0; k < S; k++) {
            sw = fmaf(wwraw[k], wwr[k], sw);
            sh = fmaf(hwraw[k], hwr[k], sh);
        }
        wwsig[t] = 1.f / (1.f + expf(-sw));
        hwsig[t] = 1.f / (1.f + expf(-sh));
    }
    __syncthreads();

    // --- outer product store ---
    float4* o = reinterpret_cast<float4*>(out + (size_t)b * IMG);
    const float4* wwv = reinterpret_cast<const float4*>(wwsig);
#pragma unroll 4
    for (int i = t; i < IMG4; i += 256) {
        int h  = i >> 5;
        int w4 = i & 31;
        float hv  = hwsig[h];
        float4 wv = wwv[w4];
        o[i] = make_float4(hv * wv.x, hv * wv.y, hv * wv.z, hv * wv.w);
    }
}

// ---------------------------------------------------------------------------
#define K2_SMEM ((2 * PLANE + 1280 + 1280 + 4 * S) * (int)sizeof(float))

extern "C" void kernel_launch(void* const* d_in, const int* in_sizes, int n_in,
                              void* d_out, int out_size) {
    const float* x      = (const float*)d_in[0];
    const float* w_conv = (const float*)d_in[1];
    const float* w_ww   = (const float*)d_in[2];
    const float* w_hw   = (const float*)d_in[3];
    const float* ww_lw  = (const float*)d_in[4];
    const float* ww_lb  = (const float*)d_in[5];
    const float* hw_lw  = (const float*)d_in[6];
    const float* hw_lb  = (const float*)d_in[7];
    float* out = (float*)d_out;

    cudaFuncSetAttribute(swa_k2, cudaFuncAttributeMaxDynamicSharedMemorySize, K2_SMEM);

    swa_k1<<<(CS * BATCH * IMG4) / 128, 128>>>(x, w_conv);
    swa_k2<<<BATCH, 256, K2_SMEM>>>(w_ww, w_hw, ww_lw, ww_lb, hw_lw, hw_lb, out);
}

// round 6
// speedup vs baseline: 1.2896x; 1.2896x over previous
#include <cuda_runtime.h>

#define BATCH 16
#define DIM   512
#define S     128
#define IMG   (S*S)
#define IMG4  (IMG/4)
#define CS    4
#define CPS   (DIM/CS)
#define SSTRIDE ((size_t)BATCH * 2 * IMG)   // split stride in g_x2p

// partial channel-reduced planes: [split][b][o(2)][h][w]  (8 MB, L2-resident)
__device__ float g_x2p[CS * BATCH * 2 * IMG];
// coldot partials: [b][c][hchunk(8)][kw(5)][w]   (640 KB)
__device__ float g_coldotp[BATCH * 2 * 8 * 5 * S];
// rowdot: [b][c][kh(5)][h]                        (80 KB)
__device__ float g_rowdot[BATCH * 2 * 5 * S];
// sigmoid vectors: [b][o(256)]  o<128 = ww, o>=128 = hw
__device__ float g_sig[BATCH * 256];

// ---------------------------------------------------------------------------
// k1: 1x1 conv channel reduction, 4-way channel split. (unchanged from R4)
// ---------------------------------------------------------------------------
__global__ __launch_bounds__(128) void swa_k1(const float* __restrict__ x,
                                              const float* __restrict__ w_conv) {
    __shared__ float w0[DIM];
    __shared__ float w1[DIM];
    for (int i = threadIdx.x; i < DIM; i += 128) {
        w0[i] = w_conv[i];
        w1[i] = w_conv[DIM + i];
    }
    __syncthreads();

    int tid   = blockIdx.x * 128 + threadIdx.x;
    int split = tid >> 16;
    int rem   = tid & 65535;
    int b     = rem >> 12;
    int p     = rem & (IMG4 - 1);

    const float4* base = reinterpret_cast<const float4*>(x)
                       + (size_t)b * DIM * IMG4 + (size_t)split * CPS * IMG4 + p;
    const int cbase = split * CPS;

    float4 a0 = make_float4(0.f, 0.f, 0.f, 0.f);
    float4 a1 = make_float4(0.f, 0.f, 0.f, 0.f);

#pragma unroll 8
    for (int c = 0; c < CPS; c++) {
        float4 v = __ldcs(base + (size_t)c * IMG4);
        float f0 = w0[cbase + c];
        float f1 = w1[cbase + c];
        a0.x = fmaf(f0, v.x, a0.x);  a0.y = fmaf(f0, v.y, a0.y);
        a0.z = fmaf(f0, v.z, a0.z);  a0.w = fmaf(f0, v.w, a0.w);
        a1.x = fmaf(f1, v.x, a1.x);  a1.y = fmaf(f1, v.y, a1.y);
        a1.z = fmaf(f1, v.z, a1.z);  a1.w = fmaf(f1, v.w, a1.w);
    }

    float4* out = reinterpret_cast<float4*>(g_x2p)
                + (size_t)split * (BATCH * 2 * IMG4)
                + (size_t)b * 2 * IMG4 + p;
    out[0]    = a0;
    out[IMG4] = a1;
}

// ---------------------------------------------------------------------------
// k2a: coldot partials + rowdot, grid (16, 24), 256 threads.
//   y < 8 : coldot chunk — thread (c,w), 16 h-rows each, 5 tap accumulators
//   y >= 8: rowdot      — warp per h (8 warps, h = (y-8)*8+wid), lanes over w
// x2 reconstructed on the fly as sum of 4 split partials (all L2-hot).
// ---------------------------------------------------------------------------
__global__ __launch_bounds__(256) void swa_k2a(const float* __restrict__ w_ww,   // [2,128,5]
                                               const float* __restrict__ w_hw) { // [2,5,128]
    const int b = blockIdx.x;
    const int y = blockIdx.y;

    if (y < 8) {
        int c = threadIdx.x >> 7;
        int w = threadIdx.x & 127;
        int h0 = y * 16;
        const float* base = g_x2p + ((size_t)b * 2 + c) * IMG + w;
        float a0 = 0.f, a1 = 0.f, a2 = 0.f, a3 = 0.f, a4 = 0.f;
#pragma unroll 4
        for (int hh = 0; hh < 16; hh++) {
            int h = h0 + hh;
            const float* p = base + h * S;
            float v = p[0] + p[SSTRIDE] + p[2 * SSTRIDE] + p[3 * SSTRIDE];
            const float* wr = w_ww + (c * S + h) * 5;
            a0 = fmaf(v, wr[0], a0);
            a1 = fmaf(v, wr[1], a1);
            a2 = fmaf(v, wr[2], a2);
            a3 = fmaf(v, wr[3], a3);
            a4 = fmaf(v, wr[4], a4);
        }
        float* dst = g_coldotp + ((((b * 2 + c) * 8 + y) * 5) * S) + w;
        dst[0*S] = a0; dst[1*S] = a1; dst[2*S] = a2; dst[3*S] = a3; dst[4*S] = a4;
    } else {
        int wid  = threadIdx.x >> 5;
        int lane = threadIdx.x & 31;
        int h    = (y - 8) * 8 + wid;
        for (int c = 0; c < 2; c++) {
            const float* base = g_x2p + ((size_t)b * 2 + c) * IMG + (size_t)h * S;
            const float* wgt  = w_hw + c * (5 * S);
            float a0 = 0.f, a1 = 0.f, a2 = 0.f, a3 = 0.f, a4 = 0.f;
#pragma unroll
            for (int w = lane; w < S; w += 32) {
                float v = base[w] + base[w + SSTRIDE] + base[w + 2 * SSTRIDE]
                        + base[w + 3 * SSTRIDE];
                a0 = fmaf(v, wgt[0*S + w], a0);
                a1 = fmaf(v, wgt[1*S + w], a1);
                a2 = fmaf(v, wgt[2*S + w], a2);
                a3 = fmaf(v, wgt[3*S + w], a3);
                a4 = fmaf(v, wgt[4*S + w], a4);
            }
#pragma unroll
            for (int sft = 16; sft; sft >>= 1) {
                a0 += __shfl_xor_sync(0xFFFFFFFFu, a0, sft);
                a1 += __shfl_xor_sync(0xFFFFFFFFu, a1, sft);
                a2 += __shfl_xor_sync(0xFFFFFFFFu, a2, sft);
                a3 += __shfl_xor_sync(0xFFFFFFFFu, a3, sft);
                a4 += __shfl_xor_sync(0xFFFFFFFFu, a4, sft);
            }
            if (lane == 0) {
                float* rd = g_rowdot + ((b * 2 + c) * 5) * S + h;
                rd[0*S] = a0; rd[1*S] = a1; rd[2*S] = a2; rd[3*S] = a3; rd[4*S] = a4;
            }
        }
    }
}

// ---------------------------------------------------------------------------
// k2b: tap-combine (redundant per block, tiny) + GEMV + sigmoid.
// grid (16, 8), 256 threads. Block (b,g) computes outputs g*32..g*32+31.
// ---------------------------------------------------------------------------
__global__ __launch_bounds__(256) void swa_k2b(const float* __restrict__ ww_lw,
                                               const float* __restrict__ ww_lb,
                                               const float* __restrict__ hw_lw,
                                               const float* __restrict__ hw_lb) {
    __shared__ float s_raw[256];   // 0..127 = wwraw, 128..255 = hwraw
    const int b = blockIdx.x;
    const int t = threadIdx.x;

    if (t < 128) {
        float s = 0.f;
#pragma unroll
        for (int k = 0; k < 5; k++) {
            int i = t - 2 + k;
            if (i >= 0 && i < S) {
                for (int c = 0; c < 2; c++)
                    for (int hc = 0; hc < 8; hc++)
                        s += g_coldotp[((((b * 2 + c) * 8 + hc) * 5 + k) * S) + i];
            }
        }
        s_raw[t] = s;
    } else {
        int ho = t - 128;
        float s = 0.f;
#pragma unroll
        for (int k = 0; k < 5; k++) {
            int i = ho - 2 + k;
            if (i >= 0 && i < S) {
                s += g_rowdot[((b * 2 + 0) * 5 + k) * S + i];
                s += g_rowdot[((b * 2 + 1) * 5 + k) * S + i];
            }
        }
        s_raw[t] = s;
    }
    __syncthreads();

    const int wid  = t >> 5;
    const int lane = t & 31;
#pragma unroll
    for (int i = 0; i < 4; i++) {
        int o  = blockIdx.y * 32 + wid * 4 + i;
        int br = o >> 7;
        int oo = o & 127;
        const float* Wrow = (br ? hw_lw : ww_lw) + oo * S;
        const float* raw  = s_raw + br * 128;
        float acc = 0.f;
#pragma unroll
        for (int k = lane; k < S; k += 32)
            acc = fmaf(raw[k], Wrow[k], acc);
#pragma unroll
        for (int sft = 16; sft; sft >>= 1)
            acc += __shfl_xor_sync(0xFFFFFFFFu, acc, sft);
        if (lane == 0) {
            float bias = (br ? hw_lb : ww_lb)[oo];
            g_sig[b * 256 + o] = 1.f / (1.f + expf(-(acc + bias)));
        }
    }
}

// ---------------------------------------------------------------------------
// k2c: outer product. grid (16, 8), 256 threads; block covers 16 h-rows.
// ---------------------------------------------------------------------------
__global__ __launch_bounds__(256) void swa_k2c(float* __restrict__ out) {
    __shared__ float s_ww[S];
    __shared__ float s_hw[16];
    const int b   = blockIdx.x;
    const int seg = blockIdx.y;
    const int t   = threadIdx.x;

    if (t < S) s_ww[t] = g_sig[b * 256 + t];
    if (t < 16) s_hw[t] = g_sig[b * 256 + 128 + seg * 16 + t];
    __syncthreads();

    float4* o = reinterpret_cast<float4*>(out + (size_t)b * IMG + seg * 16 * S);
    const float4* wwv = reinterpret_cast<const float4*>(s_ww);
#pragma unroll
    for (int i = t; i < 16 * 32; i += 256) {
        int hl = i >> 5;
        int w4 = i & 31;
        float hv  = s_hw[hl];
        float4 wv = wwv[w4];
        o[i] = make_float4(hv * wv.x, hv * wv.y, hv * wv.z, hv * wv.w);
    }
}

// ---------------------------------------------------------------------------
extern "C" void kernel_launch(void* const* d_in, const int* in_sizes, int n_in,
                              void* d_out, int out_size) {
    const float* x      = (const float*)d_in[0];
    const float* w_conv = (const float*)d_in[1];
    const float* w_ww   = (const float*)d_in[2];
    const float* w_hw   = (const float*)d_in[3];
    const float* ww_lw  = (const float*)d_in[4];
    const float* ww_lb  = (const float*)d_in[5];
    const float* hw_lw  = (const float*)d_in[6];
    const float* hw_lb  = (const float*)d_in[7];
    float* out = (float*)d_out;

    swa_k1<<<(CS * BATCH * IMG4) / 128, 128>>>(x, w_conv);
    swa_k2a<<<dim3(BATCH, 24), 256>>>(w_ww, w_hw);
    swa_k2b<<<dim3(BATCH, 8), 256>>>(ww_lw, ww_lb, hw_lw, hw_lb);
    swa_k2c<<<dim3(BATCH, 8), 256>>>(out);
}